// round 14
// baseline (speedup 1.0000x reference)
#include <cuda_runtime.h>
#include <math.h>

#define DT 0.01f
#define TPB     256
#define CHUNK   1024                   // elements per chunk
#define NCHUNK  8192                   // 8388608 / 1024
#define GRID1   512                    // k_partial: 8 warps x 2 chunks each

// Tuples (A,P,X,V): v' = A*v + V ; x' = x + P*v + X
__device__ float4 g_chunk[NCHUNK];
__device__ float4 g_pref [NCHUNK];

__device__ __forceinline__ float4 comp(float4 f, float4 g) {
    float4 r;
    r.x = g.x * f.x;
    r.y = f.y + g.y * f.x;
    r.z = f.z + g.y * f.w + g.z;
    r.w = g.x * f.w + g.w;
    return r;
}
__device__ __forceinline__ float4 ident() { return make_float4(1.f, 0.f, 0.f, 0.f); }

__device__ __forceinline__ float4 shfl_up4(float4 v, int d, unsigned m) {
    float4 r;
    r.x = __shfl_up_sync(m, v.x, d);
    r.y = __shfl_up_sync(m, v.y, d);
    r.z = __shfl_up_sync(m, v.z, d);
    r.w = __shfl_up_sync(m, v.w, d);
    return r;
}

__device__ __forceinline__ void get_coeffs(const float* mass, const float* fric,
                                           float& alpha, float& beta, float& fb) {
    float m_safe = fabsf(mass[0]) + 0.001f;
    beta  = DT / m_safe;
    fb    = fric[0] * beta;            // = 1 - alpha, no cancellation
    alpha = 1.0f - fb;
}

// ---------------- Pass 1 (R11/R13, proven ~10.3us): warp chunk tuples, batched loads ----------------
__global__ void __launch_bounds__(TPB)
k_partial(const float* __restrict__ act,
          const float* __restrict__ mass,
          const float* __restrict__ fric) {
    int lane = threadIdx.x & 31, wid = threadIdx.x >> 5;

    float alpha, beta, fb;
    get_coeffs(mass, fric, alpha, beta, fb);
    float l2a  = log2f(alpha);
    float w0   = exp2f(l2a * (float)(CHUNK - 1 - 4 * lane));
    float step = exp2f(l2a * -128.0f);
    float ai   = 1.0f / alpha;
    float ai2  = ai * ai;
    float ai3  = ai2 * ai;

    float A = alpha;
    #pragma unroll
    for (int k = 0; k < 10; k++) A *= A;                 // alpha^1024
    float denom = fb;
    if (fabsf(denom) < 1e-12f) denom = 1e-12f;
    float P = DT * alpha * (1.0f - A) / denom;

    #pragma unroll
    for (int half = 0; half < 2; half++) {
        int chunk = blockIdx.x * 8 + wid + half * (NCHUNK / 2);
        const float4* g4 = reinterpret_cast<const float4*>(act) + (size_t)chunk * (CHUNK / 4);

        float4 d[8];
        #pragma unroll
        for (int r = 0; r < 8; r++) d[r] = g4[r * 32 + lane];

        float w = w0;
        float acc0 = 0.f, acc1 = 0.f, acc2 = 0.f, acc3 = 0.f;
        float s0 = 0.f, s1 = 0.f, s2 = 0.f, s3 = 0.f;
        #pragma unroll
        for (int r = 0; r < 8; r++) {
            acc0 = fmaf(d[r].x, w, acc0);
            acc1 = fmaf(d[r].y, w, acc1);
            acc2 = fmaf(d[r].z, w, acc2);
            acc3 = fmaf(d[r].w, w, acc3);
            s0 += d[r].x; s1 += d[r].y; s2 += d[r].z; s3 += d[r].w;
            w *= step;
        }
        float W = fmaf(ai3, acc3, fmaf(ai2, acc2, fmaf(ai, acc1, acc0)));
        float S = (s0 + s1) + (s2 + s3);
        #pragma unroll
        for (int dd = 16; dd > 0; dd >>= 1) {
            W += __shfl_down_sync(0xffffffffu, W, dd);
            S += __shfl_down_sync(0xffffffffu, S, dd);
        }
        if (lane == 0) {
            float vz = beta * W;
            float xz = DT * (beta * S - alpha * vz) / denom;
            g_chunk[chunk] = make_float4(A, P, xz, vz);
        }
    }
}

// ---------------- Pass 2 (R11/R13, proven): scan 8192 chunk tuples -> exclusive prefixes ----------------
__global__ void __launch_bounds__(1024)
k_blockscan() {
    __shared__ float4 wt[32];
    int tid = threadIdx.x, lane = tid & 31, wid = tid >> 5;

    float4 c[8];
    #pragma unroll
    for (int i = 0; i < 8; i++) c[i] = g_chunk[tid * 8 + i];
    float4 val = c[0];
    #pragma unroll
    for (int i = 1; i < 8; i++) val = comp(val, c[i]);

    #pragma unroll
    for (int d = 1; d < 32; d <<= 1) {
        float4 up = shfl_up4(val, d, 0xffffffffu);
        if (lane >= d) val = comp(up, val);
    }
    if (lane == 31) wt[wid] = val;
    __syncthreads();
    if (wid == 0) {
        float4 cc = wt[lane];
        #pragma unroll
        for (int d = 1; d < 32; d <<= 1) {
            float4 up = shfl_up4(cc, d, 0xffffffffu);
            if (lane >= d) cc = comp(up, cc);
        }
        wt[lane] = cc;
    }
    __syncthreads();
    float4 wexcl = (wid == 0) ? ident() : wt[wid - 1];
    float4 lexcl = shfl_up4(val, 1, 0xffffffffu);
    if (lane == 0) lexcl = ident();
    float4 E = comp(wexcl, lexcl);

    #pragma unroll
    for (int i = 0; i < 8; i++) {
        g_pref[tid * 8 + i] = E;
        E = comp(E, c[i]);
    }
}

// ---------------- Pass 3: pointwise closed-form — 1 chunk per block, no transpose/staging ----------------
__global__ void __launch_bounds__(TPB)
k_final(const float* __restrict__ act,
        const float* __restrict__ initst,
        const float* __restrict__ mass,
        const float* __restrict__ fric,
        float2* __restrict__ out2) {
    __shared__ float2 ws[TPB / 32];
    int tid = threadIdx.x, lane = tid & 31, wid = tid >> 5;
    int chunk = blockIdx.x;

    // one coalesced float4 per thread (L2-warm after pass 1)
    const float4* g4 = reinterpret_cast<const float4*>(act) + (size_t)chunk * (CHUNK / 4);
    float4 a = g4[tid];

    float alpha, beta, fb;
    get_coeffs(mass, fric, alpha, beta, fb);
    float denom = fb;
    if (fabsf(denom) < 1e-12f) denom = 1e-12f;
    float C   = DT / denom;
    float l2a = log2f(alpha);
    float a4t  = exp2f(l2a * (float)(4 * tid));      // alpha^{4t}
    float aint = exp2f(l2a * (float)(-4 * tid));     // alpha^{-4t}  (<= ~2.8 for chunk=1024)
    float ai  = 1.0f / alpha;
    float ai2 = ai * ai;
    float ai3 = ai2 * ai;

    // local cumulative sums over the thread's 4 elements
    float gc0 = a.x;
    float gc1 = gc0 + a.y;
    float gc2 = gc1 + a.z;
    float gc3 = gc2 + a.w;
    float uc0 = a.x;
    float uc1 = fmaf(ai,  a.y, uc0);
    float uc2 = fmaf(ai2, a.z, uc1);
    float uc3 = fmaf(ai3, a.w, uc2);

    // block scan of (G, U) — plain sums with chunk-absolute weights
    float G = gc3;
    float U = aint * uc3;
    float Gown = G, Uown = U;
    #pragma unroll
    for (int d = 1; d < 32; d <<= 1) {
        float Gu = __shfl_up_sync(0xffffffffu, G, d);
        float Uu = __shfl_up_sync(0xffffffffu, U, d);
        if (lane >= d) { G += Gu; U += Uu; }
    }
    if (lane == 31) ws[wid] = make_float2(G, U);
    __syncthreads();
    if (tid < TPB / 32) {                            // lanes 0..7 of warp 0
        float2 c = ws[tid];
        #pragma unroll
        for (int d = 1; d < TPB / 32; d <<= 1) {
            float Gu = __shfl_up_sync(0xffu, c.x, d);
            float Uu = __shfl_up_sync(0xffu, c.y, d);
            if (tid >= d) { c.x += Gu; c.y += Uu; }
        }
        ws[tid] = c;
    }
    __syncthreads();
    float Ge = (wid == 0) ? 0.f : ws[wid - 1].x;
    float Ue = (wid == 0) ? 0.f : ws[wid - 1].y;
    Ge += G - Gown;                                  // exclusive = inclusive - own
    Ue += U - Uown;

    // chunk incoming state from precomputed prefix (no inter-round carry)
    float x0 = initst[0];
    float v0 = initst[1];
    float4 e = g_pref[chunk];
    float v_c = e.x * v0 + e.w;
    float x_c = x0 + e.y * v0 + e.z;

    if (chunk == 0 && tid == 0) out2[0] = make_float2(x0, v0);

    // pointwise outputs:
    //   v_k = alpha^k * (alpha^{4t+1} v_c + beta*(alpha^{4t} Ue + u_k))
    //   x_k = x_c + C*(alpha*v_c + beta*(Ge + g_k) - alpha*v_k)
    float T    = a4t * Ue;
    float sA   = alpha * (a4t * v_c);
    float base = fmaf(C * alpha, v_c, x_c);
    float a2c  = alpha * alpha;
    float a3c  = a2c * alpha;
    float Ca   = C * alpha;
    float Cb   = C * beta;

    float2* ob = out2 + 1 + (size_t)chunk * CHUNK + 4 * tid;

    float vk, xk;
    vk = sA + beta * (T + uc0);
    xk = fmaf(Cb, Ge + gc0, base) - Ca * vk;
    ob[0] = make_float2(xk, vk);

    vk = alpha * (sA + beta * (T + uc1));
    xk = fmaf(Cb, Ge + gc1, base) - Ca * vk;
    ob[1] = make_float2(xk, vk);

    vk = a2c * (sA + beta * (T + uc2));
    xk = fmaf(Cb, Ge + gc2, base) - Ca * vk;
    ob[2] = make_float2(xk, vk);

    vk = a3c * (sA + beta * (T + uc3));
    xk = fmaf(Cb, Ge + gc3, base) - Ca * vk;
    ob[3] = make_float2(xk, vk);
}

extern "C" void kernel_launch(void* const* d_in, const int* in_sizes, int n_in,
                              void* d_out, int out_size) {
    const float* init = (const float*)d_in[0];
    const float* act  = (const float*)d_in[1];
    const float* mass = (const float*)d_in[2];
    const float* fric = (const float*)d_in[3];
    float2* out2 = (float2*)d_out;

    k_partial<<<GRID1, TPB>>>(act, mass, fric);
    k_blockscan<<<1, 1024>>>();
    k_final<<<NCHUNK, TPB>>>(act, init, mass, fric, out2);
}

// round 15
// speedup vs baseline: 1.2654x; 1.2654x over previous
#include <cuda_runtime.h>
#include <math.h>

#define DT 0.01f
#define SEG     32                     // actions per thread (k_final)
#define TPB     256
#define NTILE   1024                   // tiles of 8192 for k_final
#define TILE    (TPB * SEG)            // 8192 floats per tile
#define SSTR    36                     // padded smem stride (floats) per segment
#define CHUNK   1024                   // elements per warp-chunk (k_partial)
#define NCHUNK  8192                   // 8388608 / 1024
#define GRID1   512                    // k_partial: 8 warps x 2 chunks each

// Tuples (A,P,X,V): v' = A*v + V ; x' = x + P*v + X
__device__ float4 g_chunk[NCHUNK];     // per-chunk totals
__device__ float4 g_pref [NCHUNK];     // per-chunk exclusive prefixes

__device__ __forceinline__ float4 comp(float4 f, float4 g) {
    float4 r;
    r.x = g.x * f.x;
    r.y = f.y + g.y * f.x;
    r.z = f.z + g.y * f.w + g.z;
    r.w = g.x * f.w + g.w;
    return r;
}
__device__ __forceinline__ float4 ident() { return make_float4(1.f, 0.f, 0.f, 0.f); }

__device__ __forceinline__ float4 shfl_up4(float4 v, int d, unsigned m) {
    float4 r;
    r.x = __shfl_up_sync(m, v.x, d);
    r.y = __shfl_up_sync(m, v.y, d);
    r.z = __shfl_up_sync(m, v.z, d);
    r.w = __shfl_up_sync(m, v.w, d);
    return r;
}

__device__ __forceinline__ void get_coeffs(const float* mass, const float* fric,
                                           float& alpha, float& beta, float& fb) {
    float m_safe = fabsf(mass[0]) + 0.001f;
    beta  = DT / m_safe;
    fb    = fric[0] * beta;            // = 1 - alpha, no cancellation
    alpha = 1.0f - fb;
}

// ---------------- Pass 1 (R11/R13, measured 10.27us): warp chunk tuples ----------------
__global__ void __launch_bounds__(TPB)
k_partial(const float* __restrict__ act,
          const float* __restrict__ mass,
          const float* __restrict__ fric) {
    int lane = threadIdx.x & 31, wid = threadIdx.x >> 5;

    float alpha, beta, fb;
    get_coeffs(mass, fric, alpha, beta, fb);
    float l2a  = log2f(alpha);
    float w0   = exp2f(l2a * (float)(CHUNK - 1 - 4 * lane));
    float step = exp2f(l2a * -128.0f);
    float ai   = 1.0f / alpha;
    float ai2  = ai * ai;
    float ai3  = ai2 * ai;

    float A = alpha;
    #pragma unroll
    for (int k = 0; k < 10; k++) A *= A;                 // alpha^1024
    float denom = fb;
    if (fabsf(denom) < 1e-12f) denom = 1e-12f;
    float P = DT * alpha * (1.0f - A) / denom;

    #pragma unroll
    for (int half = 0; half < 2; half++) {
        int chunk = blockIdx.x * 8 + wid + half * (NCHUNK / 2);
        const float4* g4 = reinterpret_cast<const float4*>(act) + (size_t)chunk * (CHUNK / 4);

        float4 d[8];                                     // batched: MLP = 8
        #pragma unroll
        for (int r = 0; r < 8; r++) d[r] = g4[r * 32 + lane];

        float w = w0;
        float acc0 = 0.f, acc1 = 0.f, acc2 = 0.f, acc3 = 0.f;
        float s0 = 0.f, s1 = 0.f, s2 = 0.f, s3 = 0.f;
        #pragma unroll
        for (int r = 0; r < 8; r++) {
            acc0 = fmaf(d[r].x, w, acc0);
            acc1 = fmaf(d[r].y, w, acc1);
            acc2 = fmaf(d[r].z, w, acc2);
            acc3 = fmaf(d[r].w, w, acc3);
            s0 += d[r].x; s1 += d[r].y; s2 += d[r].z; s3 += d[r].w;
            w *= step;
        }
        float W = fmaf(ai3, acc3, fmaf(ai2, acc2, fmaf(ai, acc1, acc0)));
        float S = (s0 + s1) + (s2 + s3);
        #pragma unroll
        for (int dd = 16; dd > 0; dd >>= 1) {
            W += __shfl_down_sync(0xffffffffu, W, dd);
            S += __shfl_down_sync(0xffffffffu, S, dd);
        }
        if (lane == 0) {
            float vz = beta * W;
            float xz = DT * (beta * S - alpha * vz) / denom;
            g_chunk[chunk] = make_float4(A, P, xz, vz);
        }
    }
}

// ---------------- Pass 2 (R13, proven): scan 8192 chunk tuples -> exclusive prefixes ----------------
__global__ void __launch_bounds__(1024)
k_blockscan() {
    __shared__ float4 wt[32];
    int tid = threadIdx.x, lane = tid & 31, wid = tid >> 5;

    float4 c[8];
    #pragma unroll
    for (int i = 0; i < 8; i++) c[i] = g_chunk[tid * 8 + i];
    float4 val = c[0];
    #pragma unroll
    for (int i = 1; i < 8; i++) val = comp(val, c[i]);

    #pragma unroll
    for (int d = 1; d < 32; d <<= 1) {
        float4 up = shfl_up4(val, d, 0xffffffffu);
        if (lane >= d) val = comp(up, val);
    }
    if (lane == 31) wt[wid] = val;
    __syncthreads();
    if (wid == 0) {
        float4 cc = wt[lane];
        #pragma unroll
        for (int d = 1; d < 32; d <<= 1) {
            float4 up = shfl_up4(cc, d, 0xffffffffu);
            if (lane >= d) cc = comp(up, cc);
        }
        wt[lane] = cc;
    }
    __syncthreads();
    float4 wexcl = (wid == 0) ? ident() : wt[wid - 1];
    float4 lexcl = shfl_up4(val, 1, 0xffffffffu);
    if (lane == 0) lexcl = ident();
    float4 E = comp(wexcl, lexcl);

    #pragma unroll
    for (int i = 0; i < 8; i++) {
        g_pref[tid * 8 + i] = E;
        E = comp(E, c[i]);
    }
}

// ---------------- Pass 3 (R9, measured 16.6us warm): closed-form tuples + scan + quarter replay ----------------
__global__ void __launch_bounds__(TPB)
k_final(const float* __restrict__ act,
        const float* __restrict__ initst,
        const float* __restrict__ mass,
        const float* __restrict__ fric,
        float2* __restrict__ out2) {
    __shared__ __align__(16) float s[TPB * SSTR];
    __shared__ __align__(16) float2 sout[64 * (SEG + 1)];
    __shared__ float4 wtot[TPB / 32];
    int tid = threadIdx.x, lane = tid & 31, wid = tid >> 5;
    int bid = blockIdx.x;

    {
        const float4* g4 = reinterpret_cast<const float4*>(act) + (size_t)bid * (TILE / 4);
        #pragma unroll
        for (int r = 0; r < TILE / 4 / TPB; r++) {
            int i4 = tid + TPB * r;
            float4 v = g4[i4];
            *reinterpret_cast<float4*>(&s[(i4 >> 3) * SSTR + (i4 & 7) * 4]) = v;
        }
    }
    __syncthreads();

    float alpha, beta, fb;
    get_coeffs(mass, fric, alpha, beta, fb);
    float a2  = alpha * alpha;
    float a4  = a2 * a2;
    float a8  = a4 * a4;
    float a16 = a8 * a8;
    float A   = a16 * a16;                               // alpha^32
    float a31 = a16 * a8 * a4 * a2 * alpha;              // alpha^31
    float denom = fb;
    if (fabsf(denom) < 1e-12f) denom = 1e-12f;
    float Pc = DT * alpha * (1.0f - A) / denom;
    float ai  = 1.0f / alpha;
    float ai2 = ai * ai;
    float ai4 = ai2 * ai2;

    const float* my = s + tid * SSTR;
    float acc0 = 0.f, acc1 = 0.f, acc2 = 0.f, acc3 = 0.f;
    float s0 = 0.f, s1 = 0.f, s2 = 0.f, s3 = 0.f;
    float w = a31;
    #pragma unroll
    for (int j = 0; j < SEG / 4; j++) {
        float4 a = *reinterpret_cast<const float4*>(my + 4 * j);
        acc0 = fmaf(a.x, w, acc0);
        acc1 = fmaf(a.y, w, acc1);
        acc2 = fmaf(a.z, w, acc2);
        acc3 = fmaf(a.w, w, acc3);
        s0 += a.x; s1 += a.y; s2 += a.z; s3 += a.w;
        w *= ai4;
    }
    float W = fmaf(ai2 * ai, acc3, fmaf(ai2, acc2, fmaf(ai, acc1, acc0)));
    float S = (s0 + s1) + (s2 + s3);
    float vz = beta * W;
    float xz = DT * (beta * S - alpha * vz) / denom;

    float4 val = make_float4(A, Pc, xz, vz);
    #pragma unroll
    for (int dd = 1; dd < 32; dd <<= 1) {
        float4 up = shfl_up4(val, dd, 0xffffffffu);
        if (lane >= dd) val = comp(up, val);
    }
    if (lane == 31) wtot[wid] = val;
    __syncthreads();
    if (tid < TPB / 32) {
        float4 c = wtot[tid];
        #pragma unroll
        for (int dd = 1; dd < TPB / 32; dd <<= 1) {
            float4 up = shfl_up4(c, dd, 0xffu);
            if (tid >= dd) c = comp(up, c);
        }
        wtot[tid] = c;
    }
    __syncthreads();
    float4 wexcl = (wid == 0) ? ident() : wtot[wid - 1];
    float4 lexcl = shfl_up4(val, 1, 0xffffffffu);
    if (lane == 0) lexcl = ident();
    float4 e = comp(g_pref[8 * bid], comp(wexcl, lexcl));   // chunk 8*bid == tile bid prefix

    float x0 = initst[0];
    float v0 = initst[1];
    float vin = e.x * v0 + e.w;
    float xin = x0 + e.y * v0 + e.z;

    if (bid == 0 && tid == 0) out2[0] = make_float2(x0, v0);

    float2* out_base = out2 + 1 + (size_t)bid * TILE;
    #pragma unroll
    for (int q = 0; q < 4; q++) {
        if ((tid >> 6) == q) {
            int t = tid & 63;
            float vv = vin, xx = xin;
            float2* so = sout + t * (SEG + 1);
            #pragma unroll
            for (int j = 0; j < SEG / 4; j++) {
                float4 a = *reinterpret_cast<const float4*>(my + 4 * j);
                vv = alpha * vv + beta * a.x; xx += DT * vv; so[4 * j + 0] = make_float2(xx, vv);
                vv = alpha * vv + beta * a.y; xx += DT * vv; so[4 * j + 1] = make_float2(xx, vv);
                vv = alpha * vv + beta * a.z; xx += DT * vv; so[4 * j + 2] = make_float2(xx, vv);
                vv = alpha * vv + beta * a.w; xx += DT * vv; so[4 * j + 3] = make_float2(xx, vv);
            }
        }
        __syncthreads();
        float2* gdst = out_base + q * (64 * SEG);
        #pragma unroll
        for (int w2 = 0; w2 < (64 * SEG) / TPB; w2++) {
            int i2 = tid + TPB * w2;
            gdst[i2] = sout[(i2 >> 5) * (SEG + 1) + (i2 & 31)];
        }
        __syncthreads();
    }
}

extern "C" void kernel_launch(void* const* d_in, const int* in_sizes, int n_in,
                              void* d_out, int out_size) {
    const float* init = (const float*)d_in[0];
    const float* act  = (const float*)d_in[1];
    const float* mass = (const float*)d_in[2];
    const float* fric = (const float*)d_in[3];
    float2* out2 = (float2*)d_out;

    k_partial<<<GRID1, TPB>>>(act, mass, fric);
    k_blockscan<<<1, 1024>>>();
    k_final<<<NTILE, TPB>>>(act, init, mass, fric, out2);
}

// round 16
// speedup vs baseline: 1.6964x; 1.3406x over previous
#include <cuda_runtime.h>
#include <math.h>

#define DT 0.01f
#define SEG    32                      // actions per thread (k_final)
#define TPB    256
#define NTILE  1024                    // 8388608 / 8192
#define TILE   (TPB * SEG)             // 8192 floats per tile
#define SSTR   36                      // padded smem stride (floats) per segment

// Per-tile affine tuples. (A,P,X,V): v' = A*v + V ; x' = x + P*v + X
__device__ float4 g_blk[NTILE];

__device__ __forceinline__ float4 comp(float4 f, float4 g) {
    float4 r;
    r.x = g.x * f.x;
    r.y = f.y + g.y * f.x;
    r.z = f.z + g.y * f.w + g.z;
    r.w = g.x * f.w + g.w;
    return r;
}
__device__ __forceinline__ float4 ident() { return make_float4(1.f, 0.f, 0.f, 0.f); }

__device__ __forceinline__ float4 shfl_up4(float4 v, int d, unsigned m) {
    float4 r;
    r.x = __shfl_up_sync(m, v.x, d);
    r.y = __shfl_up_sync(m, v.y, d);
    r.z = __shfl_up_sync(m, v.z, d);
    r.w = __shfl_up_sync(m, v.w, d);
    return r;
}

__device__ __forceinline__ void get_coeffs(const float* mass, const float* fric,
                                           float& alpha, float& beta, float& fb) {
    float m_safe = fabsf(mass[0]) + 0.001f;
    beta  = DT / m_safe;
    fb    = fric[0] * beta;            // = 1 - alpha, no cancellation
    alpha = 1.0f - fb;
}

// ---------------- Pass 1: per-tile tuple via two parallel reductions (R9 + batched loads) ----------------
__global__ void __launch_bounds__(TPB)
k_partial(const float* __restrict__ act,
          const float* __restrict__ mass,
          const float* __restrict__ fric) {
    __shared__ float2 wred[TPB / 32];
    int tid = threadIdx.x, lane = tid & 31, wid = tid >> 5;

    float alpha, beta, fb;
    get_coeffs(mass, fric, alpha, beta, fb);
    float l2a  = log2f(alpha);
    float w    = exp2f(l2a * (float)(8191 - 4 * tid));
    float step = exp2f(l2a * -1024.0f);

    const float4* g4 = reinterpret_cast<const float4*>(act) + (size_t)blockIdx.x * (TILE / 4);

    // batch all 8 loads before any consumption -> MLP = 8 (no occupancy cap)
    float4 d[8];
    #pragma unroll
    for (int r = 0; r < 8; r++) d[r] = g4[r * TPB + tid];

    float acc0 = 0.f, acc1 = 0.f, acc2 = 0.f, acc3 = 0.f;
    float s0 = 0.f, s1 = 0.f, s2 = 0.f, s3 = 0.f;
    #pragma unroll
    for (int r = 0; r < 8; r++) {
        acc0 = fmaf(d[r].x, w, acc0);
        acc1 = fmaf(d[r].y, w, acc1);
        acc2 = fmaf(d[r].z, w, acc2);
        acc3 = fmaf(d[r].w, w, acc3);
        s0 += d[r].x; s1 += d[r].y; s2 += d[r].z; s3 += d[r].w;
        w *= step;
    }
    float ai  = 1.0f / alpha;
    float ai2 = ai * ai;
    float W = fmaf(ai2 * ai, acc3, fmaf(ai2, acc2, fmaf(ai, acc1, acc0)));
    float S = (s0 + s1) + (s2 + s3);

    #pragma unroll
    for (int dd = 16; dd > 0; dd >>= 1) {
        W += __shfl_down_sync(0xffffffffu, W, dd);
        S += __shfl_down_sync(0xffffffffu, S, dd);
    }
    if (lane == 0) wred[wid] = make_float2(S, W);
    __syncthreads();
    if (tid == 0) {
        float St = 0.f, Wt = 0.f;
        #pragma unroll
        for (int i = 0; i < TPB / 32; i++) { St += wred[i].x; Wt += wred[i].y; }

        float A = alpha;
        #pragma unroll
        for (int j = 0; j < 13; j++) A *= A;            // alpha^8192
        float denom = fb;
        if (fabsf(denom) < 1e-12f) denom = 1e-12f;
        float P  = DT * alpha * (1.0f - A) / denom;
        float vz = beta * Wt;
        float xz = DT * (beta * St - alpha * vz) / denom;
        g_blk[blockIdx.x] = make_float4(A, P, xz, vz);
    }
}

// ---------------- Pass 2: exclusive scan of 1024 tile tuples (R9 verbatim) ----------------
__global__ void __launch_bounds__(1024)
k_blockscan() {
    __shared__ float4 wt[32];
    int tid = threadIdx.x, lane = tid & 31, wid = tid >> 5;

    float4 val = g_blk[tid];
    #pragma unroll
    for (int d = 1; d < 32; d <<= 1) {
        float4 up = shfl_up4(val, d, 0xffffffffu);
        if (lane >= d) val = comp(up, val);
    }
    if (lane == 31) wt[wid] = val;
    __syncthreads();
    if (wid == 0) {
        float4 c = wt[lane];
        #pragma unroll
        for (int d = 1; d < 32; d <<= 1) {
            float4 up = shfl_up4(c, d, 0xffffffffu);
            if (lane >= d) c = comp(up, c);
        }
        wt[lane] = c;
    }
    __syncthreads();
    float4 wexcl = (wid == 0) ? ident() : wt[wid - 1];
    float4 lexcl = shfl_up4(val, 1, 0xffffffffu);
    if (lane == 0) lexcl = ident();
    g_blk[tid] = comp(wexcl, lexcl);
}

// ---------------- Pass 3: R9 k_final verbatim (measured 16.6us warm) ----------------
__global__ void __launch_bounds__(TPB)
k_final(const float* __restrict__ act,
        const float* __restrict__ initst,
        const float* __restrict__ mass,
        const float* __restrict__ fric,
        float2* __restrict__ out2) {
    __shared__ __align__(16) float s[TPB * SSTR];          // 36864B transposed input tile
    __shared__ __align__(16) float2 sout[64 * (SEG + 1)];  // 16896B quarter staging
    __shared__ float4 wtot[TPB / 32];
    int tid = threadIdx.x, lane = tid & 31, wid = tid >> 5;
    int bid = blockIdx.x;

    {
        const float4* g4 = reinterpret_cast<const float4*>(act) + (size_t)bid * (TILE / 4);
        #pragma unroll
        for (int r = 0; r < TILE / 4 / TPB; r++) {
            int i4 = tid + TPB * r;
            float4 v = g4[i4];
            *reinterpret_cast<float4*>(&s[(i4 >> 3) * SSTR + (i4 & 7) * 4]) = v;
        }
    }
    __syncthreads();

    float alpha, beta, fb;
    get_coeffs(mass, fric, alpha, beta, fb);
    float a2  = alpha * alpha;
    float a4  = a2 * a2;
    float a8  = a4 * a4;
    float a16 = a8 * a8;
    float A   = a16 * a16;                               // alpha^32
    float a31 = a16 * a8 * a4 * a2 * alpha;              // alpha^31
    float denom = fb;
    if (fabsf(denom) < 1e-12f) denom = 1e-12f;
    float Pc = DT * alpha * (1.0f - A) / denom;
    float ai  = 1.0f / alpha;
    float ai2 = ai * ai;
    float ai4 = ai2 * ai2;

    const float* my = s + tid * SSTR;
    float acc0 = 0.f, acc1 = 0.f, acc2 = 0.f, acc3 = 0.f;
    float s0 = 0.f, s1 = 0.f, s2 = 0.f, s3 = 0.f;
    float w = a31;
    #pragma unroll
    for (int j = 0; j < SEG / 4; j++) {
        float4 a = *reinterpret_cast<const float4*>(my + 4 * j);
        acc0 = fmaf(a.x, w, acc0);
        acc1 = fmaf(a.y, w, acc1);
        acc2 = fmaf(a.z, w, acc2);
        acc3 = fmaf(a.w, w, acc3);
        s0 += a.x; s1 += a.y; s2 += a.z; s3 += a.w;
        w *= ai4;
    }
    float W = fmaf(ai2 * ai, acc3, fmaf(ai2, acc2, fmaf(ai, acc1, acc0)));
    float S = (s0 + s1) + (s2 + s3);
    float vz = beta * W;
    float xz = DT * (beta * S - alpha * vz) / denom;

    float4 val = make_float4(A, Pc, xz, vz);
    #pragma unroll
    for (int dd = 1; dd < 32; dd <<= 1) {
        float4 up = shfl_up4(val, dd, 0xffffffffu);
        if (lane >= dd) val = comp(up, val);
    }
    if (lane == 31) wtot[wid] = val;
    __syncthreads();
    if (tid < TPB / 32) {
        float4 c = wtot[tid];
        #pragma unroll
        for (int dd = 1; dd < TPB / 32; dd <<= 1) {
            float4 up = shfl_up4(c, dd, 0xffu);
            if (tid >= dd) c = comp(up, c);
        }
        wtot[tid] = c;
    }
    __syncthreads();
    float4 wexcl = (wid == 0) ? ident() : wtot[wid - 1];
    float4 lexcl = shfl_up4(val, 1, 0xffffffffu);
    if (lane == 0) lexcl = ident();
    float4 e = comp(g_blk[bid], comp(wexcl, lexcl));

    float x0 = initst[0];
    float v0 = initst[1];
    float vin = e.x * v0 + e.w;
    float xin = x0 + e.y * v0 + e.z;

    if (bid == 0 && tid == 0) out2[0] = make_float2(x0, v0);

    float2* out_base = out2 + 1 + (size_t)bid * TILE;
    #pragma unroll
    for (int q = 0; q < 4; q++) {
        if ((tid >> 6) == q) {
            int t = tid & 63;
            float vv = vin, xx = xin;
            float2* so = sout + t * (SEG + 1);
            #pragma unroll
            for (int j = 0; j < SEG / 4; j++) {
                float4 a = *reinterpret_cast<const float4*>(my + 4 * j);
                vv = alpha * vv + beta * a.x; xx += DT * vv; so[4 * j + 0] = make_float2(xx, vv);
                vv = alpha * vv + beta * a.y; xx += DT * vv; so[4 * j + 1] = make_float2(xx, vv);
                vv = alpha * vv + beta * a.z; xx += DT * vv; so[4 * j + 2] = make_float2(xx, vv);
                vv = alpha * vv + beta * a.w; xx += DT * vv; so[4 * j + 3] = make_float2(xx, vv);
            }
        }
        __syncthreads();
        float2* gdst = out_base + q * (64 * SEG);
        #pragma unroll
        for (int w2 = 0; w2 < (64 * SEG) / TPB; w2++) {
            int i2 = tid + TPB * w2;
            gdst[i2] = sout[(i2 >> 5) * (SEG + 1) + (i2 & 31)];
        }
        __syncthreads();
    }
}

extern "C" void kernel_launch(void* const* d_in, const int* in_sizes, int n_in,
                              void* d_out, int out_size) {
    const float* init = (const float*)d_in[0];
    const float* act  = (const float*)d_in[1];
    const float* mass = (const float*)d_in[2];
    const float* fric = (const float*)d_in[3];
    float2* out2 = (float2*)d_out;

    k_partial<<<NTILE, TPB>>>(act, mass, fric);
    k_blockscan<<<1, 1024>>>();
    k_final<<<NTILE, TPB>>>(act, init, mass, fric, out2);
}